// round 10
// baseline (speedup 1.0000x reference)
#include <cuda_runtime.h>
#include <cstdint>

#define DISP 49
#define GROUP 8
#define CPG 8
#define HH 96
#define WW 320
#define BB 2
#define EPSN 1e-5f
#define CHW (HH*WW)
#define PADE 49              // zero entries for the left pad
#define ROWB 12288           // smem row size: 1 KB multiple (swizzle-closed)

typedef unsigned long long u64;

__device__ __forceinline__ uint32_t swz(uint32_t o) {
    // XOR bits[6:4] with bits[9:7]: bijective within each full 1 KB block
    return o ^ ((o >> 3) & 0x70);
}
// For 32-aligned o: swz(o+16) = swz(o) ^ 16. Buffer is 1024-aligned so XOR
// on the generic pointer's low bits is exact.
__device__ __forceinline__ const char* x16(const char* p) {
    return (const char*)((uintptr_t)p ^ 16u);
}
__device__ __forceinline__ char* x16(char* p) {
    return (char*)((uintptr_t)p ^ 16u);
}
__device__ __forceinline__ u64 add2(u64 a, u64 b) {
    u64 r; asm("add.rn.f32x2 %0, %1, %2;" : "=l"(r) : "l"(a), "l"(b)); return r;
}
__device__ __forceinline__ u64 pack2(float lo, float hi) {
    u64 r; asm("mov.b64 %0, {%1, %2};" : "=l"(r) : "f"(lo), "f"(hi)); return r;
}
__device__ __forceinline__ void unpack2(u64 a, float& lo, float& hi) {
    asm("mov.b64 {%0, %1}, %2;" : "=f"(lo), "=f"(hi) : "l"(a));
}

struct C2 { u64 t6; u64 d3; };   // packed 6-ch |diff| sums + raw pair-3 diff

// Pairs 0-2 abs'd via LOP3 mask, summed packed; pair 3 returned raw (abs
// folded later into FADD operand modifiers -> free on fma pipe).
__device__ __forceinline__ C2 cost(const u64 (&xp)[4], const u64 (&wp)[4]) {
    const u64 M = 0x7fffffff7fffffffULL;
    u64 d0 = add2(xp[0], wp[0]) & M;
    u64 d1 = add2(xp[1], wp[1]) & M;
    u64 d2 = add2(xp[2], wp[2]) & M;
    u64 d3 = add2(xp[3], wp[3]);
    C2 c; c.t6 = add2(add2(d0, d1), d2); c.d3 = d3; return c;
}

// One disparity step: 2 outputs/thread. 3-slot sliding window of NEGATED yn
// entries; slot(offset o = entry - w0) = o mod 3, DM = d mod 3 compile-time.
// Refill (entry w0-d-1, consumed next step) is ISSUED FIRST -> ~1.5 steps of
// LDS-latency cover. Tail combines both outputs packed; single STG.64.
template<int DM>
__device__ __forceinline__ void step(const u64 (&xn)[2][4], u64 (&Wn)[3][4],
                                     const char* yns, int& bo, char*& op) {
    constexpr int S1 = ((1 - DM) % 3 + 3) % 3;
    constexpr int S0 = ((0 - DM) % 3 + 3) % 3;
    constexpr int SR = ((-1 - DM) % 3 + 3) % 3;

    const char* a = yns + swz((uint32_t)bo);
    const ulonglong2 lo = *(const ulonglong2*)(a);
    const ulonglong2 hi = *(const ulonglong2*)(x16(a));
    Wn[SR][0] = lo.x; Wn[SR][1] = lo.y;
    Wn[SR][2] = hi.x; Wn[SR][3] = hi.y;

    C2 c1 = cost(xn[1], Wn[S1]);
    C2 c0 = cost(xn[0], Wn[S0]);

    float a0, b0, a1, b1, t0l, t0h, t1l, t1h;
    unpack2(c0.d3, a0, b0);
    unpack2(c1.d3, a1, b1);
    unpack2(c0.t6, t0l, t0h);
    unpack2(c1.t6, t1l, t1h);
    const float s0 = fabsf(a0) + fabsf(b0);
    const float s1 = fabsf(a1) + fabsf(b1);
    const u64 res = add2(add2(pack2(t0l, t1l), pack2(t0h, t1h)), pack2(s0, s1));
    *(u64*)op = res;                              // STG.64: (r0, r1)
    op += (CHW / 2) * 8;
    bo -= 32;
}

// Process one full (b, g, h) row: prologue loads + normalize + publish +
// 49-step disparity sweep. smem pad region must already be zeroed.
__device__ __forceinline__ void do_row(const float* __restrict__ x,
                                       const float* __restrict__ y,
                                       float* __restrict__ out,
                                       char* yns, int b, int g, int h, int lx) {
    const int w0 = lx * 2;

    const float2* xp = (const float2*)(x + ((b * 64 + g * CPG) * HH + h) * WW) + lx;
    const float2* yp = (const float2*)(y + ((b * 64 + g * CPG) * HH + h) * WW) + lx;

    float xv[2][CPG], yv[2][CPG];
    float sx[2] = {0.f, 0.f}, sy[2] = {0.f, 0.f};
#pragma unroll
    for (int c = 0; c < CPG; c++) {
        const float2 tx = xp[c * (CHW / 2)];
        const float2 ty = yp[c * (CHW / 2)];
        xv[0][c] = tx.x; xv[1][c] = tx.y;
        yv[0][c] = ty.x; yv[1][c] = ty.y;
        sx[0] += tx.x * tx.x; sx[1] += tx.y * tx.y;
        sy[0] += ty.x * ty.x; sy[1] += ty.y * ty.y;
    }

    u64 xn[2][4];
    u64 Wn[3][4];
#pragma unroll
    for (int p = 0; p < 2; p++) {
        const float ix =  1.f / (sqrtf(sx[p]) + EPSN);
        const float iy = -1.f / (sqrtf(sy[p]) + EPSN);   // negated: diff = add2
#pragma unroll
        for (int q = 0; q < 4; q++) {
            xn[p][q] = pack2(xv[p][2 * q] * ix, xv[p][2 * q + 1] * ix);
            Wn[p][q] = pack2(yv[p][2 * q] * iy, yv[p][2 * q + 1] * iy);
        }
    }

    // publish -yn (entry w0+p -> offset p -> slot p, matching window init)
#pragma unroll
    for (int p = 0; p < 2; p++) {
        char* a = yns + swz((uint32_t)(w0 + p + PADE) * 32u);
        *(ulonglong2*)(a)      = make_ulonglong2(Wn[p][0], Wn[p][1]);
        *(ulonglong2*)(x16(a)) = make_ulonglong2(Wn[p][2], Wn[p][3]);
    }
    __syncthreads();

    char* op = (char*)((float2*)(out + ((b * GROUP + g) * DISP * HH + h) * WW) + lx);
    int bo = (w0 - 1 + PADE) * 32;       // step 0 refills entry w0 - 1

    // 49 steps = 1 + 16*3, phase DM = d mod 3
    step<0>(xn, Wn, yns, bo, op);
#pragma unroll 2
    for (int i = 0; i < 16; i++) {
        step<1>(xn, Wn, yns, bo, op);
        step<2>(xn, Wn, yns, bo, op);
        step<0>(xn, Wn, yns, bo, op);
    }
}

__global__ __launch_bounds__(160, 6)
void cost_volume_kernel(const float* __restrict__ x,
                        const float* __restrict__ y,
                        float* __restrict__ out) {
    __shared__ __align__(1024) char yns[ROWB];

    const int lx = threadIdx.x;          // owns w = 2lx, 2lx+1
    const int g = blockIdx.y;
    const int b = blockIdx.z;

    // zero-fill pad entries (-49..-1) ONCE: publishes never touch them, so
    // they stay valid for both rows. Pad cost Σ|xn-0| emerges naturally.
    if (lx < PADE) {
        char* a = yns + swz((uint32_t)lx * 32u);
        *(ulonglong2*)(a)      = make_ulonglong2(0ULL, 0ULL);
        *(ulonglong2*)(x16(a)) = make_ulonglong2(0ULL, 0ULL);
    }

    // two h-rows sequentially -> 768 CTAs fit ONE wave (888 slots @ occ 6)
    do_row(x, y, out, yns, b, g, blockIdx.x * 2 + 0, lx);
    __syncthreads();   // all reads of row-0 smem done before republish
    do_row(x, y, out, yns, b, g, blockIdx.x * 2 + 1, lx);
}

extern "C" void kernel_launch(void* const* d_in, const int* in_sizes, int n_in,
                              void* d_out, int out_size) {
    const float* x = (const float*)d_in[0];
    const float* y = (const float*)d_in[1];
    float* out = (float*)d_out;

    dim3 grid(HH / 2, GROUP, BB);   // 48 x 8 x 2 = 768 CTAs -> single wave
    dim3 block(160);                // 5 warps, 2 w per thread
    cost_volume_kernel<<<grid, block>>>(x, y, out);
}

// round 11
// speedup vs baseline: 1.1657x; 1.1657x over previous
#include <cuda_runtime.h>
#include <cstdint>

#define DISP 49
#define GROUP 8
#define CPG 8
#define HH 96
#define WW 320
#define BB 2
#define EPSN 1e-5f
#define CHW (HH*WW)
#define PADE 49              // zero entries for the left pad
#define ROWB 12288           // smem size: 1 KB multiple (swizzle-closed)
#define DSTR ((CHW / 2) * 8) // byte stride between disparities for one thread

typedef unsigned long long u64;

__device__ __forceinline__ uint32_t swz(uint32_t o) {
    // XOR bits[6:4] with bits[9:7]: bijective within each full 1 KB block
    return o ^ ((o >> 3) & 0x70);
}
// For 32-aligned o: swz(o+16) = swz(o) ^ 16. Buffer is 1024-aligned so XOR
// on the generic pointer's low bits is exact.
__device__ __forceinline__ const char* x16(const char* p) {
    return (const char*)((uintptr_t)p ^ 16u);
}
__device__ __forceinline__ char* x16(char* p) {
    return (char*)((uintptr_t)p ^ 16u);
}
__device__ __forceinline__ u64 add2(u64 a, u64 b) {
    u64 r; asm("add.rn.f32x2 %0, %1, %2;" : "=l"(r) : "l"(a), "l"(b)); return r;
}
__device__ __forceinline__ u64 pack2(float lo, float hi) {
    u64 r; asm("mov.b64 %0, {%1, %2};" : "=l"(r) : "f"(lo), "f"(hi)); return r;
}
__device__ __forceinline__ void unpack2(u64 a, float& lo, float& hi) {
    asm("mov.b64 {%0, %1}, %2;" : "=f"(lo), "=f"(hi) : "l"(a));
}

// Pairs 0-2 abs'd via LOP3 mask, summed packed (6 add2 + 6 LOP3); pair 3
// kept raw — abs is free via FADD |.| operand modifiers in the tail.
__device__ __forceinline__ float cost8(const u64 (&xp)[4], const u64 (&wp)[4]) {
    const u64 M = 0x7fffffff7fffffffULL;
    u64 d0 = add2(xp[0], wp[0]) & M;
    u64 d1 = add2(xp[1], wp[1]) & M;
    u64 d2 = add2(xp[2], wp[2]) & M;
    u64 d3 = add2(xp[3], wp[3]);
    float tl, th, dl, dh;
    unpack2(add2(add2(d0, d1), d2), tl, th);
    unpack2(d3, dl, dh);
    return (tl + th) + (fabsf(dl) + fabsf(dh));   // scalar tail: no pack MOVs
}

// One disparity step: 2 outputs/thread. 3-slot sliding window of NEGATED yn
// entries; slot(offset o = entry - w0) = o mod 3, DM = d mod 3 compile-time.
// KO = step index within the unrolled group: folds output/refill offsets
// into immediates (no per-step pointer updates). Refill issued FIRST; it is
// consumed mid-NEXT-step -> ~1.5 steps of LDS-latency cover.
template<int DM, int KO>
__device__ __forceinline__ void step(const u64 (&xn)[2][4], u64 (&Wn)[3][4],
                                     const char* yns, int bo, char* op) {
    constexpr int S1 = ((1 - DM) % 3 + 3) % 3;
    constexpr int S0 = ((0 - DM) % 3 + 3) % 3;
    constexpr int SR = ((-1 - DM) % 3 + 3) % 3;

    const char* a = yns + swz((uint32_t)(bo - 32 * KO));
    const ulonglong2 lo = *(const ulonglong2*)(a);
    const ulonglong2 hi = *(const ulonglong2*)(x16(a));
    Wn[SR][0] = lo.x; Wn[SR][1] = lo.y;
    Wn[SR][2] = hi.x; Wn[SR][3] = hi.y;

    const float r1 = cost8(xn[1], Wn[S1]);
    const float r0 = cost8(xn[0], Wn[S0]);
    *(float2*)(op + (long long)KO * DSTR) = make_float2(r0, r1);
}

__global__ __launch_bounds__(160, 6)
void cost_volume_kernel(const float* __restrict__ x,
                        const float* __restrict__ y,
                        float* __restrict__ out) {
    __shared__ __align__(1024) char yns[ROWB];

    const int lx = threadIdx.x;          // owns w = 2lx, 2lx+1
    const int h = blockIdx.x;
    const int g = blockIdx.y;
    const int b = blockIdx.z;
    const int w0 = lx * 2;

    // zero-fill pad entries (-49..-1): pad cost Σ|xn-0| emerges naturally
    if (lx < PADE) {
        char* a = yns + swz((uint32_t)lx * 32u);
        *(ulonglong2*)(a)      = make_ulonglong2(0ULL, 0ULL);
        *(ulonglong2*)(x16(a)) = make_ulonglong2(0ULL, 0ULL);
    }

    const float2* xp = (const float2*)(x + ((b * 64 + g * CPG) * HH + h) * WW) + lx;
    const float2* yp = (const float2*)(y + ((b * 64 + g * CPG) * HH + h) * WW) + lx;

    float xv[2][CPG], yv[2][CPG];
    float sx[2] = {0.f, 0.f}, sy[2] = {0.f, 0.f};
#pragma unroll
    for (int c = 0; c < CPG; c++) {
        const float2 tx = xp[c * (CHW / 2)];
        const float2 ty = yp[c * (CHW / 2)];
        xv[0][c] = tx.x; xv[1][c] = tx.y;
        yv[0][c] = ty.x; yv[1][c] = ty.y;
        sx[0] += tx.x * tx.x; sx[1] += tx.y * tx.y;
        sy[0] += ty.x * ty.x; sy[1] += ty.y * ty.y;
    }

    u64 xn[2][4];
    u64 Wn[3][4];
#pragma unroll
    for (int p = 0; p < 2; p++) {
        const float ix =  1.f / (sqrtf(sx[p]) + EPSN);
        const float iy = -1.f / (sqrtf(sy[p]) + EPSN);   // negated: diff = add2
#pragma unroll
        for (int q = 0; q < 4; q++) {
            xn[p][q] = pack2(xv[p][2 * q] * ix, xv[p][2 * q + 1] * ix);
            Wn[p][q] = pack2(yv[p][2 * q] * iy, yv[p][2 * q + 1] * iy);
        }
    }

    // publish -yn (entry w0+p -> offset p -> slot p, matching window init)
#pragma unroll
    for (int p = 0; p < 2; p++) {
        char* a = yns + swz((uint32_t)(w0 + p + PADE) * 32u);
        *(ulonglong2*)(a)      = make_ulonglong2(Wn[p][0], Wn[p][1]);
        *(ulonglong2*)(x16(a)) = make_ulonglong2(Wn[p][2], Wn[p][3]);
    }
    __syncthreads();

    char* op = (char*)((float2*)(out + ((b * GROUP + g) * DISP * HH + h) * WW) + lx);
    int bo = (w0 - 1 + PADE) * 32;       // step 0 refills entry w0 - 1

    // 49 steps = 1 + 16*3, phase DM = d mod 3; offsets folded as immediates
    step<0, 0>(xn, Wn, yns, bo, op);
    op += DSTR; bo -= 32;
#pragma unroll 2
    for (int i = 0; i < 16; i++) {
        step<1, 0>(xn, Wn, yns, bo, op);
        step<2, 1>(xn, Wn, yns, bo, op);
        step<0, 2>(xn, Wn, yns, bo, op);
        op += 3 * (long long)DSTR; bo -= 96;
    }
}

extern "C" void kernel_launch(void* const* d_in, const int* in_sizes, int n_in,
                              void* d_out, int out_size) {
    const float* x = (const float*)d_in[0];
    const float* y = (const float*)d_in[1];
    float* out = (float*)d_out;

    dim3 grid(HH, GROUP, BB);   // 1536 CTAs (one per b,g,h row)
    dim3 block(160);            // 5 warps, 2 w per thread
    cost_volume_kernel<<<grid, block>>>(x, y, out);
}